// round 14
// baseline (speedup 1.0000x reference)
#include <cuda_runtime.h>
#include <cuda_fp16.h>
#include <math.h>

#define ASTR 72
#define BSTR 136
#define A_ST  (128 * ASTR)
#define STG   (2 * A_ST)
#define SMEM_BYTES (3 * STG * 2) // 110592

// ---------------- static scratch ----------------
__device__ __half g_QKV[50331648];       // Q | K | V
__device__ __half g_Sh[33554432];
__device__ __half g_Oh[16777216];
__device__ __half g_Wc[2097152];         // fused wo*wf weights [(h,f), n]
__device__ __half g_Mh[8388608];
__device__ __half g_Wh[23068672];
__device__ __half g_xh[2097152], g_eh[2097152], g_X1h[2097152], g_X2h[2097152];
__device__ float g_Hf[4194304];
__device__ float g_X1f[2097152], g_X2f[2097152];
__device__ float g_RS[32768];
__device__ float g_fold[512];            // folded bias: bf + bo @ wf

#define OW_SAQ 0LL
#define OW_SAK 2097152LL
#define OW_SAV 4194304LL
#define OW_SAO 6291456LL
#define OW_SAF 8388608LL
#define OW_CAQ 10485760LL
#define OW_CAK 12582912LL
#define OW_CAV 14680064LL
#define OW_CAO 16777216LL
#define OW_CAF 18874368LL
#define OW_FC1 20971520LL
#define OW_FC2 22020096LL

// ---------------- PTX helpers ----------------
__device__ __forceinline__ void mma16816(float* d, const unsigned* a, const unsigned* b) {
    asm volatile(
        "mma.sync.aligned.m16n8k16.row.col.f32.f16.f16.f32 "
        "{%0,%1,%2,%3}, {%4,%5,%6,%7}, {%8,%9}, {%0,%1,%2,%3};"
        : "+f"(d[0]), "+f"(d[1]), "+f"(d[2]), "+f"(d[3])
        : "r"(a[0]), "r"(a[1]), "r"(a[2]), "r"(a[3]), "r"(b[0]), "r"(b[1]));
}
__device__ __forceinline__ void ldsm4(unsigned* r, unsigned a) {
    asm volatile("ldmatrix.sync.aligned.m8n8.x4.shared.b16 {%0,%1,%2,%3}, [%4];"
                 : "=r"(r[0]), "=r"(r[1]), "=r"(r[2]), "=r"(r[3]) : "r"(a));
}
__device__ __forceinline__ void ldsm4t(unsigned* r, unsigned a) {
    asm volatile("ldmatrix.sync.aligned.m8n8.x4.trans.shared.b16 {%0,%1,%2,%3}, [%4];"
                 : "=r"(r[0]), "=r"(r[1]), "=r"(r[2]), "=r"(r[3]) : "r"(a));
}
__device__ __forceinline__ void cp16(unsigned d, const void* s) {
    asm volatile("cp.async.cg.shared.global [%0], [%1], 16;" :: "r"(d), "l"(s));
}

// ---------------- GEMM: C = alpha * A*B + bias ----------------
// flags: 1 relu, 2 causal (skip masked tiles; mask diag), 4 fp32 out, 16 fp16 out,
//        32 causal K-limit, 64 multi-op (A/bias select by pq),
//        128 exp epilogue + rowsum atomics, 256 divide-by-rowsum
struct GemmP {
    const __half *Ah, *Ah2, *Bh;
    const float *bias, *biasB, *biasC;
    __half *Ch;
    float* Cf;
    float* rsum;
    int K, lda, ldb, ldc;
    long long sA1, sA2, sB1, sB2, sC1, sC2;
    int div, biasStride;
    float alpha; int flags;
};

template<bool NT>
__global__ __launch_bounds__(256, 2) void gemm_k(GemmP p) {
    extern __shared__ unsigned char raw[];
    __half* Sm = (__half*)raw;

    const int pb = blockIdx.z, pq = pb / p.div, pr = pb - pq * p.div;
    const int tid = threadIdx.x, lane = tid & 31, warp = tid >> 5;
    const int wm = warp >> 1, wn = warp & 1;
    const int m0 = blockIdx.y * 128, n0 = blockIdx.x * 128;

    if ((p.flags & 2) && n0 > m0 + 127) return;

    const int Klim = (p.flags & 32) ? (m0 + 128 < p.K ? m0 + 128 : p.K) : p.K;
    const int nch = Klim >> 6;

    const __half* Abase = ((p.flags & 64) && pq > 0) ? p.Ah2 : p.Ah;
    Abase += pq * p.sA1 + pr * p.sA2;
    const __half* Bbase = p.Bh + pq * p.sB1 + pr * p.sB2;
    const float* bias = p.bias;
    if (p.flags & 64) bias = (pq == 0) ? p.bias : ((pq == 1) ? p.biasB : p.biasC);

    const unsigned sBase = (unsigned)__cvta_generic_to_shared(Sm);

    float acc[2][8][4];
#pragma unroll
    for (int i = 0; i < 2; i++)
#pragma unroll
        for (int j = 0; j < 8; j++)
#pragma unroll
            for (int q = 0; q < 4; q++) acc[i][j][q] = 0.f;

    auto issue_stage = [&](int st, int kt) {
        const unsigned sA = sBase + 2u * (st * STG);
        const unsigned sB = sA + 2u * A_ST;
#pragma unroll
        for (int it = 0; it < 4; it++) {
            int i = tid + it * 256;
            int row = i >> 3, seg = i & 7;
            cp16(sA + 2u * (row * ASTR + seg * 8),
                 Abase + (long long)(m0 + row) * p.lda + kt + seg * 8);
        }
        if (NT) {
#pragma unroll
            for (int it = 0; it < 4; it++) {
                int i = tid + it * 256;
                int row = i >> 3, seg = i & 7;
                cp16(sB + 2u * (row * ASTR + seg * 8),
                     Bbase + (long long)(n0 + row) * p.ldb + kt + seg * 8);
            }
        } else {
#pragma unroll
            for (int it = 0; it < 4; it++) {
                int i = tid + it * 256;
                int row = i >> 4, seg = i & 15;
                cp16(sB + 2u * (row * BSTR + seg * 8),
                     Bbase + (long long)(kt + row) * p.ldb + n0 + seg * 8);
            }
        }
        asm volatile("cp.async.commit_group;");
    };

    issue_stage(0, 0);
    issue_stage(1, 64);
    asm volatile("cp.async.wait_group 1;" ::: "memory");
    __syncthreads();

    int st = 0;
    for (int c = 0; c < nch; c++) {
        if (c + 2 < nch) issue_stage((c + 2) % 3, (c + 2) * 64);
        const unsigned sA = sBase + 2u * (st * STG);
        const unsigned sB = sA + 2u * A_ST;
#pragma unroll
        for (int ks = 0; ks < 64; ks += 16) {
            unsigned ah[2][4], bh[8][2];
#pragma unroll
            for (int i = 0; i < 2; i++) {
                int row = wm * 32 + i * 16 + (lane & 15);
                int ko = ks + (lane >> 4) * 8;
                ldsm4(ah[i], sA + 2u * (row * ASTR + ko));
            }
#pragma unroll
            for (int jj = 0; jj < 4; jj++) {
                unsigned t0[4];
                if (NT) {
                    int row = wn * 64 + jj * 16 + (lane & 7) + ((lane >> 4) & 1) * 8;
                    int ko = ks + ((lane >> 3) & 1) * 8;
                    ldsm4(t0, sB + 2u * (row * ASTR + ko));
                } else {
                    int krow = ks + (lane & 7) + ((lane >> 3) & 1) * 8;
                    int ncol = wn * 64 + jj * 16 + ((lane >> 4) & 1) * 8;
                    ldsm4t(t0, sB + 2u * (krow * BSTR + ncol));
                }
                bh[2 * jj][0] = t0[0]; bh[2 * jj][1] = t0[1];
                bh[2 * jj + 1][0] = t0[2]; bh[2 * jj + 1][1] = t0[3];
            }
#pragma unroll
            for (int i = 0; i < 2; i++)
#pragma unroll
                for (int j = 0; j < 8; j++)
                    mma16816(acc[i][j], ah[i], bh[j]);
        }
        if (c + 1 < nch) {
            if (c + 2 < nch) { asm volatile("cp.async.wait_group 1;" ::: "memory"); }
            else             { asm volatile("cp.async.wait_group 0;" ::: "memory"); }
            __syncthreads();
        }
        st = (st == 2) ? 0 : st + 1;
    }

    // ---------- epilogue ----------
    __half* Ch = (p.flags & 16) ? p.Ch + pq * p.sC1 + pr * p.sC2 : nullptr;
    float*  Cf = (p.flags & 4)  ? p.Cf + pq * p.sC1 + pr * p.sC2 : nullptr;
    const int rbase = m0 + wm * 32 + (lane >> 2);
    const int cbase = n0 + wn * 64 + (lane & 3) * 2;

    float rs_inv[2][2], rs_acc[2][2];
#pragma unroll
    for (int i = 0; i < 2; i++)
#pragma unroll
        for (int h = 0; h < 2; h++) {
            rs_acc[i][h] = 0.f;
            if (p.flags & 256)
                rs_inv[i][h] = 1.f / p.rsum[(long long)pb * 1024 + rbase + i * 16 + h * 8];
        }

#pragma unroll
    for (int i = 0; i < 2; i++)
#pragma unroll
        for (int j = 0; j < 8; j++) {
            int c = cbase + j * 8;
            float b0 = 0.f, b1 = 0.f;
            if (bias) {
                b0 = bias[pr * p.biasStride + c];
                b1 = bias[pr * p.biasStride + c + 1];
            }
#pragma unroll
            for (int h = 0; h < 2; h++) {
                int r = rbase + i * 16 + h * 8;
                float v0 = acc[i][j][2 * h + 0] * p.alpha + b0;
                float v1 = acc[i][j][2 * h + 1] * p.alpha + b1;
                if (p.flags & 2) {
                    if (c > r)     v0 = -1e30f;
                    if (c + 1 > r) v1 = -1e30f;
                }
                if (p.flags & 1) { v0 = fmaxf(v0, 0.f); v1 = fmaxf(v1, 0.f); }
                if (p.flags & 128) {
                    v0 = __expf(v0); v1 = __expf(v1);
                    rs_acc[i][h] += v0 + v1;
                }
                if (p.flags & 256) { v0 *= rs_inv[i][h]; v1 *= rs_inv[i][h]; }
                long long off = (long long)r * p.ldc + c;
                if (p.flags & 4) *(float2*)(Cf + off) = make_float2(v0, v1);
                else {
                    __half2 hi; hi.x = __float2half(v0); hi.y = __float2half(v1);
                    *(__half2*)(Ch + off) = hi;
                }
            }
        }

    if (p.flags & 128) {
#pragma unroll
        for (int i = 0; i < 2; i++)
#pragma unroll
            for (int h = 0; h < 2; h++) {
                float s = rs_acc[i][h];
                s += __shfl_xor_sync(~0u, s, 1);
                s += __shfl_xor_sync(~0u, s, 2);
                if ((lane & 3) == 0)
                    atomicAdd(&p.rsum[(long long)pb * 1024 + rbase + i * 16 + h * 8], s);
            }
    }
}

// ---------------- merged fp32 -> fp16 conversion ----------------
#define NCVT 14
struct CvtP {
    const float4* src[NCVT];
    __half2* dst[NCVT];
    int n4[NCVT];
};
__global__ __launch_bounds__(256) void cvt_all_k(CvtP p) {
    const int ten = blockIdx.y;
    int i = blockIdx.x * blockDim.x + threadIdx.x;
    if (i >= p.n4[ten]) return;
    float4 v = p.src[ten][i];
    __half2 h0; h0.x = __float2half(v.x); h0.y = __float2half(v.y);
    __half2 h1; h1.x = __float2half(v.z); h1.y = __float2half(v.w);
    p.dst[ten][2 * i] = h0;
    p.dst[ten][2 * i + 1] = h1;
}

// ---------------- fold bo into final bias: fold[n] += sum_k bo[k]*wf[k,n] ----------------
__global__ __launch_bounds__(256) void bo_fold_k(const float* __restrict__ bo,
                                                 const float* __restrict__ wf,
                                                 float* __restrict__ fold) {
    __shared__ float acc[512];
    for (int i = threadIdx.x; i < 512; i += 256) acc[i] = 0.f;
    __syncthreads();
    const int k0 = blockIdx.x * 128;
    for (int k = k0; k < k0 + 128; k++) {
        float b = bo[k];
        for (int i = threadIdx.x; i < 512; i += 256)
            acc[i] += b * wf[(long long)k * 512 + i];
    }
    __syncthreads();
    for (int i = threadIdx.x; i < 512; i += 256)
        atomicAdd(&fold[i], acc[i]);
}

// ---------------- residual add (two partials) + LayerNorm ----------------
__device__ __forceinline__ float bsum(float val, float* red) {
    const int lane = threadIdx.x & 31, w = threadIdx.x >> 5;
#pragma unroll
    for (int o = 16; o; o >>= 1) val += __shfl_xor_sync(~0u, val, o);
    if (lane == 0) red[w] = val;
    __syncthreads();
    float s = red[lane & 7];
#pragma unroll
    for (int o = 4; o; o >>= 1) s += __shfl_xor_sync(~0u, s, o);
    __syncthreads();
    return s;
}

__global__ __launch_bounds__(256)
void add_ln_k(const float2* __restrict__ a, const float2* __restrict__ a2,
              const float2* __restrict__ r,
              const float* __restrict__ g, const float* __restrict__ b,
              float2* __restrict__ o, __half2* oh) {
    __shared__ float red[8];
    const long long row = blockIdx.x;
    const int t = threadIdx.x;
    float2 va = a[row * 256 + t], vb = a2[row * 256 + t], vr = r[row * 256 + t];
    float x0 = va.x + vb.x + vr.x, x1 = va.y + vb.y + vr.y;
    float mean = bsum(x0 + x1, red) * (1.f / 512.f);
    float d0 = x0 - mean, d1 = x1 - mean;
    float var = bsum(d0 * d0 + d1 * d1, red) * (1.f / 512.f);
    float inv = rsqrtf(var + 1e-5f);
    float y0 = d0 * inv * g[2 * t] + b[2 * t];
    float y1 = d1 * inv * g[2 * t + 1] + b[2 * t + 1];
    o[row * 256 + t] = make_float2(y0, y1);
    if (oh) {
        __half2 hh; hh.x = __float2half(y0); hh.y = __float2half(y1);
        oh[row * 256 + t] = hh;
    }
}

// ---------------- host ----------------
static void launch_gemm(bool nt, const GemmP& p, int M, int N, int batch) {
    dim3 g(N / 128, M / 128, batch);
    if (nt) gemm_k<true><<<g, 256, SMEM_BYTES>>>(p);
    else    gemm_k<false><<<g, 256, SMEM_BYTES>>>(p);
}

extern "C" void kernel_launch(void* const* d_in, const int* in_sizes, int n_in,
                              void* d_out, int out_size) {
    const float* x   = (const float*)d_in[0];
    const float* enc = (const float*)d_in[1];
    const float* sa_wq = (const float*)d_in[2];  const float* sa_bq = (const float*)d_in[3];
    const float* sa_wk = (const float*)d_in[4];  const float* sa_bk = (const float*)d_in[5];
    const float* sa_wv = (const float*)d_in[6];  const float* sa_bv = (const float*)d_in[7];
    const float* sa_wo = (const float*)d_in[8];  const float* sa_bo = (const float*)d_in[9];
    const float* sa_wf = (const float*)d_in[10]; const float* sa_bf = (const float*)d_in[11];
    const float* ca_wq = (const float*)d_in[12]; const float* ca_bq = (const float*)d_in[13];
    const float* ca_wk = (const float*)d_in[14]; const float* ca_bk = (const float*)d_in[15];
    const float* ca_wv = (const float*)d_in[16]; const float* ca_bv = (const float*)d_in[17];
    const float* ca_wo = (const float*)d_in[18]; const float* ca_bo = (const float*)d_in[19];
    const float* ca_wf = (const float*)d_in[20]; const float* ca_bf = (const float*)d_in[21];
    const float* ln1_g = (const float*)d_in[22]; const float* ln1_b = (const float*)d_in[23];
    const float* ln2_g = (const float*)d_in[24]; const float* ln2_b = (const float*)d_in[25];
    const float* ln3_g = (const float*)d_in[26]; const float* ln3_b = (const float*)d_in[27];
    const float* fc1_w = (const float*)d_in[28]; const float* fc1_b = (const float*)d_in[29];
    const float* fc2_w = (const float*)d_in[30]; const float* fc2_b = (const float*)d_in[31];

    cudaFuncSetAttribute((const void*)gemm_k<false>,
                         cudaFuncAttributeMaxDynamicSharedMemorySize, SMEM_BYTES);
    cudaFuncSetAttribute((const void*)gemm_k<true>,
                         cudaFuncAttributeMaxDynamicSharedMemorySize, SMEM_BYTES);

    __half *QKV, *Sh, *Oh, *Wc, *Mh, *Wh, *xh, *eh, *X1h, *X2h;
    float *Hf, *X1f, *X2f, *RS, *fold;
    cudaGetSymbolAddress((void**)&QKV, g_QKV);
    cudaGetSymbolAddress((void**)&Sh, g_Sh);
    cudaGetSymbolAddress((void**)&Oh, g_Oh);
    cudaGetSymbolAddress((void**)&Wc, g_Wc);
    cudaGetSymbolAddress((void**)&Mh, g_Mh);
    cudaGetSymbolAddress((void**)&Wh, g_Wh);
    cudaGetSymbolAddress((void**)&xh, g_xh);  cudaGetSymbolAddress((void**)&eh, g_eh);
    cudaGetSymbolAddress((void**)&X1h, g_X1h); cudaGetSymbolAddress((void**)&X2h, g_X2h);
    cudaGetSymbolAddress((void**)&Hf, g_Hf);
    cudaGetSymbolAddress((void**)&X1f, g_X1f);
    cudaGetSymbolAddress((void**)&X2f, g_X2f);
    cudaGetSymbolAddress((void**)&RS, g_RS);
    cudaGetSymbolAddress((void**)&fold, g_fold);

    __half* Qh = QKV;
    __half* Kh = QKV + 16777216;
    __half* Vh = QKV + 33554432;
    float* Hf2 = Hf + 2097152;

    // one merged conversion launch
    {
        CvtP cp{};
        const float* srcs[NCVT] = { x, enc, sa_wq, sa_wk, sa_wv, sa_wo, sa_wf,
                                    ca_wq, ca_wk, ca_wv, ca_wo, ca_wf, fc1_w, fc2_w };
        __half* dsts[NCVT] = { xh, eh, Wh + OW_SAQ, Wh + OW_SAK, Wh + OW_SAV,
                               Wh + OW_SAO, Wh + OW_SAF, Wh + OW_CAQ, Wh + OW_CAK,
                               Wh + OW_CAV, Wh + OW_CAO, Wh + OW_CAF,
                               Wh + OW_FC1, Wh + OW_FC2 };
        for (int i = 0; i < NCVT; i++) {
            cp.src[i] = (const float4*)srcs[i];
            cp.dst[i] = (__half2*)dsts[i];
            cp.n4[i] = (i >= 12) ? 262144 : 524288;
        }
        cvt_all_k<<<dim3(2048, NCVT), 256>>>(cp);
    }

    const float ISC = 0.044194173824159216f;  // 1/sqrt(512)

    auto runMHA = [&](const __half* aq, const __half* akv, long long oqkv,
                      long long oo, long long of,
                      const float* bq, const float* bk, const float* bv,
                      const float* bo, const float* bfb, const float* wf32, bool causal) {
        GemmP p{};
        // fused Q/K/V projections: batch 24
        p.Ah = aq; p.Ah2 = akv; p.Bh = Wh + oqkv;
        p.bias = bq; p.biasB = bk; p.biasC = bv;
        p.Ch = QKV;
        p.K = 512; p.lda = 512; p.ldb = 512; p.ldc = 4096;
        p.sB1 = 2097152; p.sB2 = 262144; p.sC1 = 16777216; p.sC2 = 512;
        p.div = 8; p.biasStride = 512; p.alpha = 1.f; p.flags = 16 | 64;
        launch_gemm(false, p, 4096, 512, 24);
        // Wc[h] = wo_h @ wf_block_h  (batch 8, tiny)
        p = GemmP{};
        p.Ah = Wh + oo; p.Bh = Wh + of; p.Ch = Wc;
        p.K = 512; p.lda = 512; p.ldb = 512; p.ldc = 512;
        p.sA2 = 262144; p.sB2 = 262144; p.sC2 = 262144;
        p.div = 8; p.alpha = 1.f; p.flags = 16;
        launch_gemm(false, p, 512, 512, 8);
        // fold = bf + bo @ wf  (fp32 originals)
        cudaMemcpyAsync(fold, bfb, 512 * sizeof(float), cudaMemcpyDeviceToDevice, 0);
        bo_fold_k<<<32, 256>>>(bo, wf32, fold);
        // rowsum <- 0
        cudaMemsetAsync(RS, 0, 32768 * sizeof(float), 0);
        // scores: exp(Q K^T / sqrt(512)) + rowsum atomics
        p = GemmP{};
        p.Ah = Qh; p.Bh = Kh; p.Ch = Sh; p.rsum = RS;
        p.K = 512; p.lda = 4096; p.ldb = 4096; p.ldc = 1024;
        p.sA1 = 4194304; p.sA2 = 512; p.sB1 = 4194304; p.sB2 = 512;
        p.sC1 = 8388608; p.sC2 = 1048576;
        p.div = 8; p.alpha = ISC; p.flags = 128 | 16 | (causal ? 2 : 0);
        launch_gemm(true, p, 1024, 1024, 32);
        // O = P V / rowsum  (causal K-limit); Oh layout [(b,s), (h,f)]
        p = GemmP{};
        p.Ah = Sh; p.Bh = Vh; p.Ch = Oh; p.rsum = RS;
        p.K = 1024; p.lda = 1024; p.ldb = 4096; p.ldc = 4096;
        p.sA1 = 8388608; p.sA2 = 1048576; p.sB1 = 4194304; p.sB2 = 512;
        p.sC1 = 4194304; p.sC2 = 512;
        p.div = 8; p.alpha = 1.f; p.flags = 256 | 16 | (causal ? 32 : 0);
        launch_gemm(false, p, 1024, 512, 32);
        // fused out+concat projection: Oh [4096 x 4096] @ Wc [4096 x 512], split-K=2
        p = GemmP{};
        p.Ah = Oh; p.Ah2 = Oh; p.Bh = Wc;
        p.bias = fold; p.biasB = nullptr; p.biasC = nullptr;
        p.Cf = Hf;
        p.K = 2048; p.lda = 4096; p.ldb = 512; p.ldc = 512;
        p.sA1 = 2048; p.sB1 = 2048LL * 512; p.sC1 = 2097152;
        p.div = 1; p.alpha = 1.f; p.flags = 4 | 64;
        launch_gemm(false, p, 4096, 512, 2);
    };

    // self-attention (causal) + LN1
    runMHA(xh, xh, OW_SAQ, OW_SAO, OW_SAF, sa_bq, sa_bk, sa_bv, sa_bo, sa_bf, sa_wf, true);
    add_ln_k<<<4096, 256>>>((const float2*)Hf, (const float2*)Hf2, (const float2*)x,
                            ln1_g, ln1_b, (float2*)X1f, (__half2*)X1h);

    // cross-attention + LN2
    runMHA(X1h, eh, OW_CAQ, OW_CAO, OW_CAF, ca_bq, ca_bk, ca_bv, ca_bo, ca_bf, ca_wf, false);
    add_ln_k<<<4096, 256>>>((const float2*)Hf, (const float2*)Hf2, (const float2*)X1f,
                            ln2_g, ln2_b, (float2*)X2f, (__half2*)X2h);

    // FFN
    {
        GemmP p{};
        p.Ah = X2h; p.Bh = Wh + OW_FC1; p.bias = fc1_b; p.Ch = Mh;
        p.K = 512; p.lda = 512; p.ldb = 2048; p.ldc = 2048;
        p.div = 1; p.biasStride = 0; p.alpha = 1.f; p.flags = 16 | 1;
        launch_gemm(false, p, 4096, 2048, 1);

        // FC2: split-K=2
        p = GemmP{};
        p.Ah = Mh; p.Ah2 = Mh; p.Bh = Wh + OW_FC2;
        p.bias = fc2_b; p.biasB = nullptr; p.biasC = nullptr;
        p.Cf = Hf;
        p.K = 1024; p.lda = 2048; p.ldb = 512; p.ldc = 512;
        p.sA1 = 1024; p.sB1 = 1024LL * 512; p.sC1 = 2097152;
        p.div = 1; p.alpha = 1.f; p.flags = 4 | 64;
        launch_gemm(false, p, 4096, 512, 2);
    }
    add_ln_k<<<4096, 256>>>((const float2*)Hf, (const float2*)Hf2, (const float2*)X2f,
                            ln3_g, ln3_b, (float2*)d_out, nullptr);
}

// round 15
// speedup vs baseline: 1.2153x; 1.2153x over previous
#include <cuda_runtime.h>
#include <cuda_fp16.h>
#include <math.h>

#define ASTR 72
#define BSTR 136
#define A_ST  (128 * ASTR)
#define STG   (2 * A_ST)
#define SMEM_BYTES (3 * STG * 2) // 110592

// ---------------- static scratch ----------------
__device__ __half g_QKV[50331648];       // Q | K | V
__device__ __half g_Sh[33554432];
__device__ __half g_Oh[16777216];
__device__ __half g_Wc[2097152];         // fused wo*wf weights [(h,f), n]
__device__ __half g_Mh[8388608];
__device__ __half g_Wh[23068672];
__device__ __half g_xh[2097152], g_eh[2097152], g_X1h[2097152], g_X2h[2097152];
__device__ float g_Hf[4194304];
__device__ float g_X1f[2097152], g_X2f[2097152];
__device__ float g_RS[32768];
__device__ float g_fold[512];            // folded bias: bf + bo @ wf

#define OW_SAQ 0LL
#define OW_SAK 2097152LL
#define OW_SAV 4194304LL
#define OW_SAO 6291456LL
#define OW_SAF 8388608LL
#define OW_CAQ 10485760LL
#define OW_CAK 12582912LL
#define OW_CAV 14680064LL
#define OW_CAO 16777216LL
#define OW_CAF 18874368LL
#define OW_FC1 20971520LL
#define OW_FC2 22020096LL

// ---------------- PTX helpers ----------------
__device__ __forceinline__ void mma16816(float* d, const unsigned* a, const unsigned* b) {
    asm volatile(
        "mma.sync.aligned.m16n8k16.row.col.f32.f16.f16.f32 "
        "{%0,%1,%2,%3}, {%4,%5,%6,%7}, {%8,%9}, {%0,%1,%2,%3};"
        : "+f"(d[0]), "+f"(d[1]), "+f"(d[2]), "+f"(d[3])
        : "r"(a[0]), "r"(a[1]), "r"(a[2]), "r"(a[3]), "r"(b[0]), "r"(b[1]));
}
__device__ __forceinline__ void ldsm4(unsigned* r, unsigned a) {
    asm volatile("ldmatrix.sync.aligned.m8n8.x4.shared.b16 {%0,%1,%2,%3}, [%4];"
                 : "=r"(r[0]), "=r"(r[1]), "=r"(r[2]), "=r"(r[3]) : "r"(a));
}
__device__ __forceinline__ void ldsm4t(unsigned* r, unsigned a) {
    asm volatile("ldmatrix.sync.aligned.m8n8.x4.trans.shared.b16 {%0,%1,%2,%3}, [%4];"
                 : "=r"(r[0]), "=r"(r[1]), "=r"(r[2]), "=r"(r[3]) : "r"(a));
}
__device__ __forceinline__ void cp16(unsigned d, const void* s) {
    asm volatile("cp.async.cg.shared.global [%0], [%1], 16;" :: "r"(d), "l"(s));
}

// ---------------- GEMM: C = alpha * A*B + bias ----------------
// flags: 1 relu, 2 causal (skip masked tiles; mask diag), 4 fp32 out, 16 fp16 out,
//        32 causal K-limit, 64 multi-op (A/bias select by pq),
//        128 exp epilogue + rowsum atomics, 256 divide-by-rowsum
struct GemmP {
    const __half *Ah, *Ah2, *Bh;
    const float *bias, *biasB, *biasC;
    __half *Ch;
    float* Cf;
    float* rsum;
    int K, lda, ldb, ldc;
    long long sA1, sA2, sB1, sB2, sC1, sC2;
    int div, biasStride;
    float alpha; int flags;
};

template<bool NT>
__global__ __launch_bounds__(256, 2) void gemm_k(GemmP p) {
    extern __shared__ unsigned char raw[];
    __half* Sm = (__half*)raw;

    const int pb = blockIdx.z, pq = pb / p.div, pr = pb - pq * p.div;
    const int tid = threadIdx.x, lane = tid & 31, warp = tid >> 5;
    const int wm = warp >> 1, wn = warp & 1;
    const int m0 = blockIdx.y * 128, n0 = blockIdx.x * 128;

    if ((p.flags & 2) && n0 > m0 + 127) return;

    const int Klim = (p.flags & 32) ? (m0 + 128 < p.K ? m0 + 128 : p.K) : p.K;
    const int nch = Klim >> 6;

    const __half* Abase = ((p.flags & 64) && pq > 0) ? p.Ah2 : p.Ah;
    Abase += pq * p.sA1 + pr * p.sA2;
    const __half* Bbase = p.Bh + pq * p.sB1 + pr * p.sB2;
    const float* bias = p.bias;
    if (p.flags & 64) bias = (pq == 0) ? p.bias : ((pq == 1) ? p.biasB : p.biasC);

    const unsigned sBase = (unsigned)__cvta_generic_to_shared(Sm);

    float acc[2][8][4];
#pragma unroll
    for (int i = 0; i < 2; i++)
#pragma unroll
        for (int j = 0; j < 8; j++)
#pragma unroll
            for (int q = 0; q < 4; q++) acc[i][j][q] = 0.f;

    auto issue_stage = [&](int st, int kt) {
        const unsigned sA = sBase + 2u * (st * STG);
        const unsigned sB = sA + 2u * A_ST;
#pragma unroll
        for (int it = 0; it < 4; it++) {
            int i = tid + it * 256;
            int row = i >> 3, seg = i & 7;
            cp16(sA + 2u * (row * ASTR + seg * 8),
                 Abase + (long long)(m0 + row) * p.lda + kt + seg * 8);
        }
        if (NT) {
#pragma unroll
            for (int it = 0; it < 4; it++) {
                int i = tid + it * 256;
                int row = i >> 3, seg = i & 7;
                cp16(sB + 2u * (row * ASTR + seg * 8),
                     Bbase + (long long)(n0 + row) * p.ldb + kt + seg * 8);
            }
        } else {
#pragma unroll
            for (int it = 0; it < 4; it++) {
                int i = tid + it * 256;
                int row = i >> 4, seg = i & 15;
                cp16(sB + 2u * (row * BSTR + seg * 8),
                     Bbase + (long long)(kt + row) * p.ldb + n0 + seg * 8);
            }
        }
        asm volatile("cp.async.commit_group;");
    };

    issue_stage(0, 0);
    issue_stage(1, 64);
    asm volatile("cp.async.wait_group 1;" ::: "memory");
    __syncthreads();

    int st = 0;
    for (int c = 0; c < nch; c++) {
        if (c + 2 < nch) issue_stage((c + 2) % 3, (c + 2) * 64);
        const unsigned sA = sBase + 2u * (st * STG);
        const unsigned sB = sA + 2u * A_ST;
#pragma unroll
        for (int ks = 0; ks < 64; ks += 16) {
            unsigned ah[2][4], bh[8][2];
#pragma unroll
            for (int i = 0; i < 2; i++) {
                int row = wm * 32 + i * 16 + (lane & 15);
                int ko = ks + (lane >> 4) * 8;
                ldsm4(ah[i], sA + 2u * (row * ASTR + ko));
            }
#pragma unroll
            for (int jj = 0; jj < 4; jj++) {
                unsigned t0[4];
                if (NT) {
                    int row = wn * 64 + jj * 16 + (lane & 7) + ((lane >> 4) & 1) * 8;
                    int ko = ks + ((lane >> 3) & 1) * 8;
                    ldsm4(t0, sB + 2u * (row * ASTR + ko));
                } else {
                    int krow = ks + (lane & 7) + ((lane >> 3) & 1) * 8;
                    int ncol = wn * 64 + jj * 16 + ((lane >> 4) & 1) * 8;
                    ldsm4t(t0, sB + 2u * (krow * BSTR + ncol));
                }
                bh[2 * jj][0] = t0[0]; bh[2 * jj][1] = t0[1];
                bh[2 * jj + 1][0] = t0[2]; bh[2 * jj + 1][1] = t0[3];
            }
#pragma unroll
            for (int i = 0; i < 2; i++)
#pragma unroll
                for (int j = 0; j < 8; j++)
                    mma16816(acc[i][j], ah[i], bh[j]);
        }
        if (c + 1 < nch) {
            if (c + 2 < nch) { asm volatile("cp.async.wait_group 1;" ::: "memory"); }
            else             { asm volatile("cp.async.wait_group 0;" ::: "memory"); }
            __syncthreads();
        }
        st = (st == 2) ? 0 : st + 1;
    }

    // ---------- epilogue ----------
    __half* Ch = (p.flags & 16) ? p.Ch + pq * p.sC1 + pr * p.sC2 : nullptr;
    float*  Cf = (p.flags & 4)  ? p.Cf + pq * p.sC1 + pr * p.sC2 : nullptr;
    const int rbase = m0 + wm * 32 + (lane >> 2);
    const int cbase = n0 + wn * 64 + (lane & 3) * 2;

    float rs_inv[2][2], rs_acc[2][2];
#pragma unroll
    for (int i = 0; i < 2; i++)
#pragma unroll
        for (int h = 0; h < 2; h++) {
            rs_acc[i][h] = 0.f;
            if (p.flags & 256)
                rs_inv[i][h] = 1.f / p.rsum[(long long)pb * 1024 + rbase + i * 16 + h * 8];
        }

#pragma unroll
    for (int i = 0; i < 2; i++)
#pragma unroll
        for (int j = 0; j < 8; j++) {
            int c = cbase + j * 8;
            float b0 = 0.f, b1 = 0.f;
            if (bias) {
                b0 = bias[pr * p.biasStride + c];
                b1 = bias[pr * p.biasStride + c + 1];
            }
#pragma unroll
            for (int h = 0; h < 2; h++) {
                int r = rbase + i * 16 + h * 8;
                float v0 = acc[i][j][2 * h + 0] * p.alpha + b0;
                float v1 = acc[i][j][2 * h + 1] * p.alpha + b1;
                if (p.flags & 2) {
                    if (c > r)     v0 = -1e30f;
                    if (c + 1 > r) v1 = -1e30f;
                }
                if (p.flags & 1) { v0 = fmaxf(v0, 0.f); v1 = fmaxf(v1, 0.f); }
                if (p.flags & 128) {
                    v0 = __expf(v0); v1 = __expf(v1);
                    rs_acc[i][h] += v0 + v1;
                }
                if (p.flags & 256) { v0 *= rs_inv[i][h]; v1 *= rs_inv[i][h]; }
                long long off = (long long)r * p.ldc + c;
                if (p.flags & 4) *(float2*)(Cf + off) = make_float2(v0, v1);
                else {
                    __half2 hi; hi.x = __float2half(v0); hi.y = __float2half(v1);
                    *(__half2*)(Ch + off) = hi;
                }
            }
        }

    if (p.flags & 128) {
#pragma unroll
        for (int i = 0; i < 2; i++)
#pragma unroll
            for (int h = 0; h < 2; h++) {
                float s = rs_acc[i][h];
                s += __shfl_xor_sync(~0u, s, 1);
                s += __shfl_xor_sync(~0u, s, 2);
                if ((lane & 3) == 0)
                    atomicAdd(&p.rsum[(long long)pb * 1024 + rbase + i * 16 + h * 8], s);
            }
    }
}

// ---------------- merged fp32 -> fp16 conversion ----------------
#define NCVT 14
struct CvtP {
    const float4* src[NCVT];
    __half2* dst[NCVT];
    int n4[NCVT];
};
__global__ __launch_bounds__(256) void cvt_all_k(CvtP p) {
    const int ten = blockIdx.y;
    int i = blockIdx.x * blockDim.x + threadIdx.x;
    if (i >= p.n4[ten]) return;
    float4 v = p.src[ten][i];
    __half2 h0; h0.x = __float2half(v.x); h0.y = __float2half(v.y);
    __half2 h1; h1.x = __float2half(v.z); h1.y = __float2half(v.w);
    p.dst[ten][2 * i] = h0;
    p.dst[ten][2 * i + 1] = h1;
}

// ---------------- fast bias fold: fold[n] += sum_k bo[k]*wf[k,n] ----------------
// 32 blocks x 512 threads; block b handles k in [b*128, b*128+128); thread t owns n=t.
__global__ __launch_bounds__(512) void bo_fold_k(const float* __restrict__ bo,
                                                 const float* __restrict__ wf,
                                                 float* __restrict__ fold) {
    __shared__ float sbo[128];
    const int t = threadIdx.x;
    const int k0 = blockIdx.x * 128;
    if (t < 128) sbo[t] = bo[k0 + t];
    __syncthreads();
    float acc = 0.f;
    const float* wp = wf + (long long)k0 * 512 + t;
#pragma unroll 8
    for (int k = 0; k < 128; k++)
        acc += sbo[k] * wp[(long long)k * 512];
    atomicAdd(&fold[t], acc);
}

// ---------------- residual add (two partials) + LayerNorm ----------------
__device__ __forceinline__ float bsum(float val, float* red) {
    const int lane = threadIdx.x & 31, w = threadIdx.x >> 5;
#pragma unroll
    for (int o = 16; o; o >>= 1) val += __shfl_xor_sync(~0u, val, o);
    if (lane == 0) red[w] = val;
    __syncthreads();
    float s = red[lane & 7];
#pragma unroll
    for (int o = 4; o; o >>= 1) s += __shfl_xor_sync(~0u, s, o);
    __syncthreads();
    return s;
}

__global__ __launch_bounds__(256)
void add_ln_k(const float2* __restrict__ a, const float2* __restrict__ a2,
              const float2* __restrict__ r,
              const float* __restrict__ g, const float* __restrict__ b,
              float2* __restrict__ o, __half2* oh) {
    __shared__ float red[8];
    const long long row = blockIdx.x;
    const int t = threadIdx.x;
    float2 va = a[row * 256 + t], vb = a2[row * 256 + t], vr = r[row * 256 + t];
    float x0 = va.x + vb.x + vr.x, x1 = va.y + vb.y + vr.y;
    float mean = bsum(x0 + x1, red) * (1.f / 512.f);
    float d0 = x0 - mean, d1 = x1 - mean;
    float var = bsum(d0 * d0 + d1 * d1, red) * (1.f / 512.f);
    float inv = rsqrtf(var + 1e-5f);
    float y0 = d0 * inv * g[2 * t] + b[2 * t];
    float y1 = d1 * inv * g[2 * t + 1] + b[2 * t + 1];
    o[row * 256 + t] = make_float2(y0, y1);
    if (oh) {
        __half2 hh; hh.x = __float2half(y0); hh.y = __float2half(y1);
        oh[row * 256 + t] = hh;
    }
}

// ---------------- host ----------------
static void launch_gemm(bool nt, const GemmP& p, int M, int N, int batch) {
    dim3 g(N / 128, M / 128, batch);
    if (nt) gemm_k<true><<<g, 256, SMEM_BYTES>>>(p);
    else    gemm_k<false><<<g, 256, SMEM_BYTES>>>(p);
}

extern "C" void kernel_launch(void* const* d_in, const int* in_sizes, int n_in,
                              void* d_out, int out_size) {
    const float* x   = (const float*)d_in[0];
    const float* enc = (const float*)d_in[1];
    const float* sa_wq = (const float*)d_in[2];  const float* sa_bq = (const float*)d_in[3];
    const float* sa_wk = (const float*)d_in[4];  const float* sa_bk = (const float*)d_in[5];
    const float* sa_wv = (const float*)d_in[6];  const float* sa_bv = (const float*)d_in[7];
    const float* sa_wo = (const float*)d_in[8];  const float* sa_bo = (const float*)d_in[9];
    const float* sa_wf = (const float*)d_in[10]; const float* sa_bf = (const float*)d_in[11];
    const float* ca_wq = (const float*)d_in[12]; const float* ca_bq = (const float*)d_in[13];
    const float* ca_wk = (const float*)d_in[14]; const float* ca_bk = (const float*)d_in[15];
    const float* ca_wv = (const float*)d_in[16]; const float* ca_bv = (const float*)d_in[17];
    const float* ca_wo = (const float*)d_in[18]; const float* ca_bo = (const float*)d_in[19];
    const float* ca_wf = (const float*)d_in[20]; const float* ca_bf = (const float*)d_in[21];
    const float* ln1_g = (const float*)d_in[22]; const float* ln1_b = (const float*)d_in[23];
    const float* ln2_g = (const float*)d_in[24]; const float* ln2_b = (const float*)d_in[25];
    const float* ln3_g = (const float*)d_in[26]; const float* ln3_b = (const float*)d_in[27];
    const float* fc1_w = (const float*)d_in[28]; const float* fc1_b = (const float*)d_in[29];
    const float* fc2_w = (const float*)d_in[30]; const float* fc2_b = (const float*)d_in[31];

    cudaFuncSetAttribute((const void*)gemm_k<false>,
                         cudaFuncAttributeMaxDynamicSharedMemorySize, SMEM_BYTES);
    cudaFuncSetAttribute((const void*)gemm_k<true>,
                         cudaFuncAttributeMaxDynamicSharedMemorySize, SMEM_BYTES);

    __half *QKV, *Sh, *Oh, *Wc, *Mh, *Wh, *xh, *eh, *X1h, *X2h;
    float *Hf, *X1f, *X2f, *RS, *fold;
    cudaGetSymbolAddress((void**)&QKV, g_QKV);
    cudaGetSymbolAddress((void**)&Sh, g_Sh);
    cudaGetSymbolAddress((void**)&Oh, g_Oh);
    cudaGetSymbolAddress((void**)&Wc, g_Wc);
    cudaGetSymbolAddress((void**)&Mh, g_Mh);
    cudaGetSymbolAddress((void**)&Wh, g_Wh);
    cudaGetSymbolAddress((void**)&xh, g_xh);  cudaGetSymbolAddress((void**)&eh, g_eh);
    cudaGetSymbolAddress((void**)&X1h, g_X1h); cudaGetSymbolAddress((void**)&X2h, g_X2h);
    cudaGetSymbolAddress((void**)&Hf, g_Hf);
    cudaGetSymbolAddress((void**)&X1f, g_X1f);
    cudaGetSymbolAddress((void**)&X2f, g_X2f);
    cudaGetSymbolAddress((void**)&RS, g_RS);
    cudaGetSymbolAddress((void**)&fold, g_fold);

    __half* Qh = QKV;
    __half* Kh = QKV + 16777216;
    __half* Vh = QKV + 33554432;
    float* Hf2 = Hf + 2097152;

    // one merged conversion launch
    {
        CvtP cp{};
        const float* srcs[NCVT] = { x, enc, sa_wq, sa_wk, sa_wv, sa_wo, sa_wf,
                                    ca_wq, ca_wk, ca_wv, ca_wo, ca_wf, fc1_w, fc2_w };
        __half* dsts[NCVT] = { xh, eh, Wh + OW_SAQ, Wh + OW_SAK, Wh + OW_SAV,
                               Wh + OW_SAO, Wh + OW_SAF, Wh + OW_CAQ, Wh + OW_CAK,
                               Wh + OW_CAV, Wh + OW_CAO, Wh + OW_CAF,
                               Wh + OW_FC1, Wh + OW_FC2 };
        for (int i = 0; i < NCVT; i++) {
            cp.src[i] = (const float4*)srcs[i];
            cp.dst[i] = (__half2*)dsts[i];
            cp.n4[i] = (i >= 12) ? 262144 : 524288;
        }
        cvt_all_k<<<dim3(2048, NCVT), 256>>>(cp);
    }

    const float ISC = 0.044194173824159216f;  // 1/sqrt(512)

    auto runMHA = [&](const __half* aq, const __half* akv, long long oqkv,
                      long long oo, long long of,
                      const float* bq, const float* bk, const float* bv,
                      const float* bo, const float* bfb, const float* wf32, bool causal) {
        GemmP p{};
        // fused Q/K/V projections: batch 24
        p.Ah = aq; p.Ah2 = akv; p.Bh = Wh + oqkv;
        p.bias = bq; p.biasB = bk; p.biasC = bv;
        p.Ch = QKV;
        p.K = 512; p.lda = 512; p.ldb = 512; p.ldc = 4096;
        p.sB1 = 2097152; p.sB2 = 262144; p.sC1 = 16777216; p.sC2 = 512;
        p.div = 8; p.biasStride = 512; p.alpha = 1.f; p.flags = 16 | 64;
        launch_gemm(false, p, 4096, 512, 24);
        // Wc[h] = wo_h @ wf_block_h  (batch 8, tiny)
        p = GemmP{};
        p.Ah = Wh + oo; p.Bh = Wh + of; p.Ch = Wc;
        p.K = 512; p.lda = 512; p.ldb = 512; p.ldc = 512;
        p.sA2 = 262144; p.sB2 = 262144; p.sC2 = 262144;
        p.div = 8; p.alpha = 1.f; p.flags = 16;
        launch_gemm(false, p, 512, 512, 8);
        // fold = bf + bo @ wf  (fp32 originals)
        cudaMemcpyAsync(fold, bfb, 512 * sizeof(float), cudaMemcpyDeviceToDevice, 0);
        bo_fold_k<<<32, 512>>>(bo, wf32, fold);
        // rowsum <- 0
        cudaMemsetAsync(RS, 0, 32768 * sizeof(float), 0);
        // scores: exp(Q K^T / sqrt(512)) + rowsum atomics
        p = GemmP{};
        p.Ah = Qh; p.Bh = Kh; p.Ch = Sh; p.rsum = RS;
        p.K = 512; p.lda = 4096; p.ldb = 4096; p.ldc = 1024;
        p.sA1 = 4194304; p.sA2 = 512; p.sB1 = 4194304; p.sB2 = 512;
        p.sC1 = 8388608; p.sC2 = 1048576;
        p.div = 8; p.alpha = ISC; p.flags = 128 | 16 | (causal ? 2 : 0);
        launch_gemm(true, p, 1024, 1024, 32);
        // O = P V / rowsum  (causal K-limit); Oh layout [(b,s), (h,f)]
        p = GemmP{};
        p.Ah = Sh; p.Bh = Vh; p.Ch = Oh; p.rsum = RS;
        p.K = 1024; p.lda = 1024; p.ldb = 4096; p.ldc = 4096;
        p.sA1 = 8388608; p.sA2 = 1048576; p.sB1 = 4194304; p.sB2 = 512;
        p.sC1 = 4194304; p.sC2 = 512;
        p.div = 8; p.alpha = 1.f; p.flags = 256 | 16 | (causal ? 32 : 0);
        launch_gemm(false, p, 1024, 512, 32);
        // fused out+concat projection: Oh [4096 x 4096] @ Wc [4096 x 512], split-K=2
        p = GemmP{};
        p.Ah = Oh; p.Ah2 = Oh; p.Bh = Wc;
        p.bias = fold; p.biasB = nullptr; p.biasC = nullptr;
        p.Cf = Hf;
        p.K = 2048; p.lda = 4096; p.ldb = 512; p.ldc = 512;
        p.sA1 = 2048; p.sB1 = 2048LL * 512; p.sC1 = 2097152;
        p.div = 1; p.alpha = 1.f; p.flags = 4 | 64;
        launch_gemm(false, p, 4096, 512, 2);
    };

    // self-attention (causal) + LN1
    runMHA(xh, xh, OW_SAQ, OW_SAO, OW_SAF, sa_bq, sa_bk, sa_bv, sa_bo, sa_bf, sa_wf, true);
    add_ln_k<<<4096, 256>>>((const float2*)Hf, (const float2*)Hf2, (const float2*)x,
                            ln1_g, ln1_b, (float2*)X1f, (__half2*)X1h);

    // cross-attention + LN2
    runMHA(X1h, eh, OW_CAQ, OW_CAO, OW_CAF, ca_bq, ca_bk, ca_bv, ca_bo, ca_bf, ca_wf, false);
    add_ln_k<<<4096, 256>>>((const float2*)Hf, (const float2*)Hf2, (const float2*)X1f,
                            ln2_g, ln2_b, (float2*)X2f, (__half2*)X2h);

    // FFN
    {
        GemmP p{};
        p.Ah = X2h; p.Bh = Wh + OW_FC1; p.bias = fc1_b; p.Ch = Mh;
        p.K = 512; p.lda = 512; p.ldb = 2048; p.ldc = 2048;
        p.div = 1; p.biasStride = 0; p.alpha = 1.f; p.flags = 16 | 1;
        launch_gemm(false, p, 4096, 2048, 1);

        // FC2: split-K=2
        p = GemmP{};
        p.Ah = Mh; p.Ah2 = Mh; p.Bh = Wh + OW_FC2;
        p.bias = fc2_b; p.biasB = nullptr; p.biasC = nullptr;
        p.Cf = Hf;
        p.K = 1024; p.lda = 2048; p.ldb = 512; p.ldc = 512;
        p.sA1 = 1024; p.sB1 = 1024LL * 512; p.sC1 = 2097152;
        p.div = 1; p.alpha = 1.f; p.flags = 4 | 64;
        launch_gemm(false, p, 4096, 512, 2);
    }
    add_ln_k<<<4096, 256>>>((const float2*)Hf, (const float2*)Hf2, (const float2*)X2f,
                            ln3_g, ln3_b, (float2*)d_out, nullptr);
}

// round 16
// speedup vs baseline: 1.2353x; 1.0165x over previous
#include <cuda_runtime.h>
#include <cuda_fp16.h>
#include <math.h>

#define ASTR 72
#define BSTR 136
#define A_ST  (128 * ASTR)
#define STG   (2 * A_ST)
#define SMEM_BYTES (3 * STG * 2) // 110592

// ---------------- static scratch ----------------
__device__ __half g_QKV[50331648];       // Q | K | V
__device__ __half g_Sh[33554432];
__device__ __half g_Oh[16777216];
__device__ __half g_Wc[4194304];         // fused wo*wf weights, sa | ca
__device__ __half g_Mh[8388608];
__device__ __half g_Wh[23068672];
__device__ __half g_xh[2097152], g_eh[2097152], g_X1h[2097152], g_X2h[2097152];
__device__ float g_Hf[4194304];
__device__ float g_X1f[2097152], g_X2f[2097152];
__device__ float g_RS[32768];
__device__ float g_fold[1024];           // folded bias: bf + bo @ wf, sa | ca

#define OW_SAQ 0LL
#define OW_SAK 2097152LL
#define OW_SAV 4194304LL
#define OW_SAO 6291456LL
#define OW_SAF 8388608LL
#define OW_CAQ 10485760LL
#define OW_CAK 12582912LL
#define OW_CAV 14680064LL
#define OW_CAO 16777216LL
#define OW_CAF 18874368LL
#define OW_FC1 20971520LL
#define OW_FC2 22020096LL

// ---------------- PTX helpers ----------------
__device__ __forceinline__ void mma16816(float* d, const unsigned* a, const unsigned* b) {
    asm volatile(
        "mma.sync.aligned.m16n8k16.row.col.f32.f16.f16.f32 "
        "{%0,%1,%2,%3}, {%4,%5,%6,%7}, {%8,%9}, {%0,%1,%2,%3};"
        : "+f"(d[0]), "+f"(d[1]), "+f"(d[2]), "+f"(d[3])
        : "r"(a[0]), "r"(a[1]), "r"(a[2]), "r"(a[3]), "r"(b[0]), "r"(b[1]));
}
__device__ __forceinline__ void ldsm4(unsigned* r, unsigned a) {
    asm volatile("ldmatrix.sync.aligned.m8n8.x4.shared.b16 {%0,%1,%2,%3}, [%4];"
                 : "=r"(r[0]), "=r"(r[1]), "=r"(r[2]), "=r"(r[3]) : "r"(a));
}
__device__ __forceinline__ void ldsm4t(unsigned* r, unsigned a) {
    asm volatile("ldmatrix.sync.aligned.m8n8.x4.trans.shared.b16 {%0,%1,%2,%3}, [%4];"
                 : "=r"(r[0]), "=r"(r[1]), "=r"(r[2]), "=r"(r[3]) : "r"(a));
}
__device__ __forceinline__ void cp16(unsigned d, const void* s) {
    asm volatile("cp.async.cg.shared.global [%0], [%1], 16;" :: "r"(d), "l"(s));
}

// ---------------- GEMM: C = alpha * A*B + bias ----------------
// flags: 1 relu, 2 causal (skip masked tiles; mask diag), 4 fp32 out, 16 fp16 out,
//        32 causal K-limit, 64 multi-op (A/bias select by pq),
//        128 exp epilogue + rowsum atomics, 256 divide-by-rowsum
struct GemmP {
    const __half *Ah, *Ah2, *Bh;
    const float *bias, *biasB, *biasC;
    __half *Ch;
    float* Cf;
    float* rsum;
    int K, lda, ldb, ldc;
    long long sA1, sA2, sB1, sB2, sC1, sC2;
    int div, biasStride;
    float alpha; int flags;
};

template<bool NT>
__global__ __launch_bounds__(256, 2) void gemm_k(GemmP p) {
    extern __shared__ unsigned char raw[];
    __half* Sm = (__half*)raw;

    const int pb = blockIdx.z, pq = pb / p.div, pr = pb - pq * p.div;
    const int tid = threadIdx.x, lane = tid & 31, warp = tid >> 5;
    const int wm = warp >> 1, wn = warp & 1;
    const int m0 = blockIdx.y * 128, n0 = blockIdx.x * 128;

    if ((p.flags & 2) && n0 > m0 + 127) return;

    const int Klim = (p.flags & 32) ? (m0 + 128 < p.K ? m0 + 128 : p.K) : p.K;
    const int nch = Klim >> 6;

    const __half* Abase = ((p.flags & 64) && pq > 0) ? p.Ah2 : p.Ah;
    Abase += pq * p.sA1 + pr * p.sA2;
    const __half* Bbase = p.Bh + pq * p.sB1 + pr * p.sB2;
    const float* bias = p.bias;
    if (p.flags & 64) bias = (pq == 0) ? p.bias : ((pq == 1) ? p.biasB : p.biasC);

    const unsigned sBase = (unsigned)__cvta_generic_to_shared(Sm);

    float acc[2][8][4];
#pragma unroll
    for (int i = 0; i < 2; i++)
#pragma unroll
        for (int j = 0; j < 8; j++)
#pragma unroll
            for (int q = 0; q < 4; q++) acc[i][j][q] = 0.f;

    auto issue_stage = [&](int st, int kt) {
        const unsigned sA = sBase + 2u * (st * STG);
        const unsigned sB = sA + 2u * A_ST;
#pragma unroll
        for (int it = 0; it < 4; it++) {
            int i = tid + it * 256;
            int row = i >> 3, seg = i & 7;
            cp16(sA + 2u * (row * ASTR + seg * 8),
                 Abase + (long long)(m0 + row) * p.lda + kt + seg * 8);
        }
        if (NT) {
#pragma unroll
            for (int it = 0; it < 4; it++) {
                int i = tid + it * 256;
                int row = i >> 3, seg = i & 7;
                cp16(sB + 2u * (row * ASTR + seg * 8),
                     Bbase + (long long)(n0 + row) * p.ldb + kt + seg * 8);
            }
        } else {
#pragma unroll
            for (int it = 0; it < 4; it++) {
                int i = tid + it * 256;
                int row = i >> 4, seg = i & 15;
                cp16(sB + 2u * (row * BSTR + seg * 8),
                     Bbase + (long long)(kt + row) * p.ldb + n0 + seg * 8);
            }
        }
        asm volatile("cp.async.commit_group;");
    };

    issue_stage(0, 0);
    issue_stage(1, 64);
    asm volatile("cp.async.wait_group 1;" ::: "memory");
    __syncthreads();

    int st = 0;
    for (int c = 0; c < nch; c++) {
        if (c + 2 < nch) issue_stage((c + 2) % 3, (c + 2) * 64);
        const unsigned sA = sBase + 2u * (st * STG);
        const unsigned sB = sA + 2u * A_ST;
#pragma unroll
        for (int ks = 0; ks < 64; ks += 16) {
            unsigned ah[2][4], bh[8][2];
#pragma unroll
            for (int i = 0; i < 2; i++) {
                int row = wm * 32 + i * 16 + (lane & 15);
                int ko = ks + (lane >> 4) * 8;
                ldsm4(ah[i], sA + 2u * (row * ASTR + ko));
            }
#pragma unroll
            for (int jj = 0; jj < 4; jj++) {
                unsigned t0[4];
                if (NT) {
                    int row = wn * 64 + jj * 16 + (lane & 7) + ((lane >> 4) & 1) * 8;
                    int ko = ks + ((lane >> 3) & 1) * 8;
                    ldsm4(t0, sB + 2u * (row * ASTR + ko));
                } else {
                    int krow = ks + (lane & 7) + ((lane >> 3) & 1) * 8;
                    int ncol = wn * 64 + jj * 16 + ((lane >> 4) & 1) * 8;
                    ldsm4t(t0, sB + 2u * (krow * BSTR + ncol));
                }
                bh[2 * jj][0] = t0[0]; bh[2 * jj][1] = t0[1];
                bh[2 * jj + 1][0] = t0[2]; bh[2 * jj + 1][1] = t0[3];
            }
#pragma unroll
            for (int i = 0; i < 2; i++)
#pragma unroll
                for (int j = 0; j < 8; j++)
                    mma16816(acc[i][j], ah[i], bh[j]);
        }
        if (c + 1 < nch) {
            if (c + 2 < nch) { asm volatile("cp.async.wait_group 1;" ::: "memory"); }
            else             { asm volatile("cp.async.wait_group 0;" ::: "memory"); }
            __syncthreads();
        }
        st = (st == 2) ? 0 : st + 1;
    }

    // ---------- epilogue ----------
    __half* Ch = (p.flags & 16) ? p.Ch + pq * p.sC1 + pr * p.sC2 : nullptr;
    float*  Cf = (p.flags & 4)  ? p.Cf + pq * p.sC1 + pr * p.sC2 : nullptr;
    const int rbase = m0 + wm * 32 + (lane >> 2);
    const int cbase = n0 + wn * 64 + (lane & 3) * 2;

    float rs_inv[2][2], rs_acc[2][2];
#pragma unroll
    for (int i = 0; i < 2; i++)
#pragma unroll
        for (int h = 0; h < 2; h++) {
            rs_acc[i][h] = 0.f;
            if (p.flags & 256)
                rs_inv[i][h] = 1.f / p.rsum[(long long)pb * 1024 + rbase + i * 16 + h * 8];
        }

#pragma unroll
    for (int i = 0; i < 2; i++)
#pragma unroll
        for (int j = 0; j < 8; j++) {
            int c = cbase + j * 8;
            float b0 = 0.f, b1 = 0.f;
            if (bias) {
                b0 = bias[pr * p.biasStride + c];
                b1 = bias[pr * p.biasStride + c + 1];
            }
#pragma unroll
            for (int h = 0; h < 2; h++) {
                int r = rbase + i * 16 + h * 8;
                float v0 = acc[i][j][2 * h + 0] * p.alpha + b0;
                float v1 = acc[i][j][2 * h + 1] * p.alpha + b1;
                if (p.flags & 2) {
                    if (c > r)     v0 = -1e30f;
                    if (c + 1 > r) v1 = -1e30f;
                }
                if (p.flags & 1) { v0 = fmaxf(v0, 0.f); v1 = fmaxf(v1, 0.f); }
                if (p.flags & 128) {
                    v0 = __expf(v0); v1 = __expf(v1);
                    rs_acc[i][h] += v0 + v1;
                }
                if (p.flags & 256) { v0 *= rs_inv[i][h]; v1 *= rs_inv[i][h]; }
                long long off = (long long)r * p.ldc + c;
                if (p.flags & 4) *(float2*)(Cf + off) = make_float2(v0, v1);
                else {
                    __half2 hi; hi.x = __float2half(v0); hi.y = __float2half(v1);
                    *(__half2*)(Ch + off) = hi;
                }
            }
        }

    if (p.flags & 128) {
#pragma unroll
        for (int i = 0; i < 2; i++)
#pragma unroll
            for (int h = 0; h < 2; h++) {
                float s = rs_acc[i][h];
                s += __shfl_xor_sync(~0u, s, 1);
                s += __shfl_xor_sync(~0u, s, 2);
                if ((lane & 3) == 0)
                    atomicAdd(&p.rsum[(long long)pb * 1024 + rbase + i * 16 + h * 8], s);
            }
    }
}

// ---------------- merged fp32 -> fp16 conversion ----------------
#define NCVT 14
struct CvtP {
    const float4* src[NCVT];
    __half2* dst[NCVT];
    int n4[NCVT];
};
__global__ __launch_bounds__(256) void cvt_all_k(CvtP p) {
    const int ten = blockIdx.y;
    int i = blockIdx.x * blockDim.x + threadIdx.x;
    if (i >= p.n4[ten]) return;
    float4 v = p.src[ten][i];
    __half2 h0; h0.x = __float2half(v.x); h0.y = __float2half(v.y);
    __half2 h1; h1.x = __float2half(v.z); h1.y = __float2half(v.w);
    p.dst[ten][2 * i] = h0;
    p.dst[ten][2 * i + 1] = h1;
}

// ---------------- both bias folds in one launch ----------------
// grid (128, 2), block 512: y selects (sa, ca); block x covers 32 k-rows.
// fold pre-zeroed; block 0 adds bf.
__global__ __launch_bounds__(512) void bo_fold2_k(const float* __restrict__ bo0,
                                                  const float* __restrict__ wf0,
                                                  const float* __restrict__ bf0,
                                                  const float* __restrict__ bo1,
                                                  const float* __restrict__ wf1,
                                                  const float* __restrict__ bf1,
                                                  float* __restrict__ fold) {
    const int which = blockIdx.y;
    const float* bo = which ? bo1 : bo0;
    const float* wf = which ? wf1 : wf0;
    const float* bf = which ? bf1 : bf0;
    float* fd = fold + which * 512;
    __shared__ float sbo[32];
    const int t = threadIdx.x;
    const int k0 = blockIdx.x * 32;
    if (t < 32) sbo[t] = bo[k0 + t];
    __syncthreads();
    float acc = (blockIdx.x == 0) ? bf[t] : 0.f;
    const float* wp = wf + (long long)k0 * 512 + t;
#pragma unroll
    for (int k = 0; k < 32; k++)
        acc += sbo[k] * wp[(long long)k * 512];
    atomicAdd(&fd[t], acc);
}

// ---------------- residual add (two partials) + LayerNorm ----------------
__device__ __forceinline__ float bsum(float val, float* red) {
    const int lane = threadIdx.x & 31, w = threadIdx.x >> 5;
#pragma unroll
    for (int o = 16; o; o >>= 1) val += __shfl_xor_sync(~0u, val, o);
    if (lane == 0) red[w] = val;
    __syncthreads();
    float s = red[lane & 7];
#pragma unroll
    for (int o = 4; o; o >>= 1) s += __shfl_xor_sync(~0u, s, o);
    __syncthreads();
    return s;
}

__global__ __launch_bounds__(256)
void add_ln_k(const float2* __restrict__ a, const float2* __restrict__ a2,
              const float2* __restrict__ r,
              const float* __restrict__ g, const float* __restrict__ b,
              float2* __restrict__ o, __half2* oh) {
    __shared__ float red[8];
    const long long row = blockIdx.x;
    const int t = threadIdx.x;
    float2 va = a[row * 256 + t], vb = a2[row * 256 + t], vr = r[row * 256 + t];
    float x0 = va.x + vb.x + vr.x, x1 = va.y + vb.y + vr.y;
    float mean = bsum(x0 + x1, red) * (1.f / 512.f);
    float d0 = x0 - mean, d1 = x1 - mean;
    float var = bsum(d0 * d0 + d1 * d1, red) * (1.f / 512.f);
    float inv = rsqrtf(var + 1e-5f);
    float y0 = d0 * inv * g[2 * t] + b[2 * t];
    float y1 = d1 * inv * g[2 * t + 1] + b[2 * t + 1];
    o[row * 256 + t] = make_float2(y0, y1);
    if (oh) {
        __half2 hh; hh.x = __float2half(y0); hh.y = __float2half(y1);
        oh[row * 256 + t] = hh;
    }
}

// ---------------- host ----------------
static void launch_gemm(bool nt, const GemmP& p, int M, int N, int batch) {
    dim3 g(N / 128, M / 128, batch);
    if (nt) gemm_k<true><<<g, 256, SMEM_BYTES>>>(p);
    else    gemm_k<false><<<g, 256, SMEM_BYTES>>>(p);
}

extern "C" void kernel_launch(void* const* d_in, const int* in_sizes, int n_in,
                              void* d_out, int out_size) {
    const float* x   = (const float*)d_in[0];
    const float* enc = (const float*)d_in[1];
    const float* sa_wq = (const float*)d_in[2];  const float* sa_bq = (const float*)d_in[3];
    const float* sa_wk = (const float*)d_in[4];  const float* sa_bk = (const float*)d_in[5];
    const float* sa_wv = (const float*)d_in[6];  const float* sa_bv = (const float*)d_in[7];
    const float* sa_wo = (const float*)d_in[8];  const float* sa_bo = (const float*)d_in[9];
    const float* sa_wf = (const float*)d_in[10]; const float* sa_bf = (const float*)d_in[11];
    const float* ca_wq = (const float*)d_in[12]; const float* ca_bq = (const float*)d_in[13];
    const float* ca_wk = (const float*)d_in[14]; const float* ca_bk = (const float*)d_in[15];
    const float* ca_wv = (const float*)d_in[16]; const float* ca_bv = (const float*)d_in[17];
    const float* ca_wo = (const float*)d_in[18]; const float* ca_bo = (const float*)d_in[19];
    const float* ca_wf = (const float*)d_in[20]; const float* ca_bf = (const float*)d_in[21];
    const float* ln1_g = (const float*)d_in[22]; const float* ln1_b = (const float*)d_in[23];
    const float* ln2_g = (const float*)d_in[24]; const float* ln2_b = (const float*)d_in[25];
    const float* ln3_g = (const float*)d_in[26]; const float* ln3_b = (const float*)d_in[27];
    const float* fc1_w = (const float*)d_in[28]; const float* fc1_b = (const float*)d_in[29];
    const float* fc2_w = (const float*)d_in[30]; const float* fc2_b = (const float*)d_in[31];

    cudaFuncSetAttribute((const void*)gemm_k<false>,
                         cudaFuncAttributeMaxDynamicSharedMemorySize, SMEM_BYTES);
    cudaFuncSetAttribute((const void*)gemm_k<true>,
                         cudaFuncAttributeMaxDynamicSharedMemorySize, SMEM_BYTES);

    __half *QKV, *Sh, *Oh, *Wc, *Mh, *Wh, *xh, *eh, *X1h, *X2h;
    float *Hf, *X1f, *X2f, *RS, *fold;
    cudaGetSymbolAddress((void**)&QKV, g_QKV);
    cudaGetSymbolAddress((void**)&Sh, g_Sh);
    cudaGetSymbolAddress((void**)&Oh, g_Oh);
    cudaGetSymbolAddress((void**)&Wc, g_Wc);
    cudaGetSymbolAddress((void**)&Mh, g_Mh);
    cudaGetSymbolAddress((void**)&Wh, g_Wh);
    cudaGetSymbolAddress((void**)&xh, g_xh);  cudaGetSymbolAddress((void**)&eh, g_eh);
    cudaGetSymbolAddress((void**)&X1h, g_X1h); cudaGetSymbolAddress((void**)&X2h, g_X2h);
    cudaGetSymbolAddress((void**)&Hf, g_Hf);
    cudaGetSymbolAddress((void**)&X1f, g_X1f);
    cudaGetSymbolAddress((void**)&X2f, g_X2f);
    cudaGetSymbolAddress((void**)&RS, g_RS);
    cudaGetSymbolAddress((void**)&fold, g_fold);

    __half* Qh = QKV;
    __half* Kh = QKV + 16777216;
    __half* Vh = QKV + 33554432;
    float* Hf2 = Hf + 2097152;

    // one merged conversion launch
    {
        CvtP cp{};
        const float* srcs[NCVT] = { x, enc, sa_wq, sa_wk, sa_wv, sa_wo, sa_wf,
                                    ca_wq, ca_wk, ca_wv, ca_wo, ca_wf, fc1_w, fc2_w };
        __half* dsts[NCVT] = { xh, eh, Wh + OW_SAQ, Wh + OW_SAK, Wh + OW_SAV,
                               Wh + OW_SAO, Wh + OW_SAF, Wh + OW_CAQ, Wh + OW_CAK,
                               Wh + OW_CAV, Wh + OW_CAO, Wh + OW_CAF,
                               Wh + OW_FC1, Wh + OW_FC2 };
        for (int i = 0; i < NCVT; i++) {
            cp.src[i] = (const float4*)srcs[i];
            cp.dst[i] = (__half2*)dsts[i];
            cp.n4[i] = (i >= 12) ? 262144 : 524288;
        }
        cvt_all_k<<<dim3(2048, NCVT), 256>>>(cp);
    }

    // ---- upfront weight-only preprocessing ----
    {
        // both Wc products in one batch-16 launch
        GemmP p{};
        p.Ah = Wh + OW_SAO; p.Ah2 = Wh + OW_CAO; p.Bh = Wh + OW_SAF;
        p.Ch = Wc;
        p.K = 512; p.lda = 512; p.ldb = 512; p.ldc = 512;
        p.sA1 = 0; p.sA2 = 262144;
        p.sB1 = OW_CAF - OW_SAF; p.sB2 = 262144;
        p.sC1 = 2097152; p.sC2 = 262144;
        p.div = 8; p.alpha = 1.f; p.flags = 16 | 64;
        launch_gemm(false, p, 512, 512, 16);
        // both bias folds
        cudaMemsetAsync(fold, 0, 1024 * sizeof(float), 0);
        bo_fold2_k<<<dim3(128, 2), 512>>>(sa_bo, sa_wf, sa_bf, ca_bo, ca_wf, ca_bf, fold);
    }

    const float ISC = 0.044194173824159216f;  // 1/sqrt(512)

    auto runMHA = [&](const __half* aq, const __half* akv, long long oqkv,
                      const __half* wcBase, const float* foldBase, bool causal,
                      const float* bq, const float* bk, const float* bv) {
        GemmP p{};
        // fused Q/K/V projections: batch 24
        p.Ah = aq; p.Ah2 = akv; p.Bh = Wh + oqkv;
        p.bias = bq; p.biasB = bk; p.biasC = bv;
        p.Ch = QKV;
        p.K = 512; p.lda = 512; p.ldb = 512; p.ldc = 4096;
        p.sB1 = 2097152; p.sB2 = 262144; p.sC1 = 16777216; p.sC2 = 512;
        p.div = 8; p.biasStride = 512; p.alpha = 1.f; p.flags = 16 | 64;
        launch_gemm(false, p, 4096, 512, 24);
        // rowsum <- 0
        cudaMemsetAsync(RS, 0, 32768 * sizeof(float), 0);
        // scores: exp(Q K^T / sqrt(512)) + rowsum atomics
        p = GemmP{};
        p.Ah = Qh; p.Bh = Kh; p.Ch = Sh; p.rsum = RS;
        p.K = 512; p.lda = 4096; p.ldb = 4096; p.ldc = 1024;
        p.sA1 = 4194304; p.sA2 = 512; p.sB1 = 4194304; p.sB2 = 512;
        p.sC1 = 8388608; p.sC2 = 1048576;
        p.div = 8; p.alpha = ISC; p.flags = 128 | 16 | (causal ? 2 : 0);
        launch_gemm(true, p, 1024, 1024, 32);
        // O = P V / rowsum  (causal K-limit); Oh layout [(b,s), (h,f)]
        p = GemmP{};
        p.Ah = Sh; p.Bh = Vh; p.Ch = Oh; p.rsum = RS;
        p.K = 1024; p.lda = 1024; p.ldb = 4096; p.ldc = 4096;
        p.sA1 = 8388608; p.sA2 = 1048576; p.sB1 = 4194304; p.sB2 = 512;
        p.sC1 = 4194304; p.sC2 = 512;
        p.div = 8; p.alpha = 1.f; p.flags = 256 | 16 | (causal ? 32 : 0);
        launch_gemm(false, p, 1024, 512, 32);
        // fused out+concat projection: Oh [4096 x 4096] @ Wc [4096 x 512], split-K=2
        p = GemmP{};
        p.Ah = Oh; p.Ah2 = Oh; p.Bh = wcBase;
        p.bias = foldBase; p.biasB = nullptr; p.biasC = nullptr;
        p.Cf = Hf;
        p.K = 2048; p.lda = 4096; p.ldb = 512; p.ldc = 512;
        p.sA1 = 2048; p.sB1 = 2048LL * 512; p.sC1 = 2097152;
        p.div = 1; p.alpha = 1.f; p.flags = 4 | 64;
        launch_gemm(false, p, 4096, 512, 2);
    };

    // self-attention (causal) + LN1
    runMHA(xh, xh, OW_SAQ, Wc, fold, true, sa_bq, sa_bk, sa_bv);
    add_ln_k<<<4096, 256>>>((const float2*)Hf, (const float2*)Hf2, (const float2*)x,
                            ln1_g, ln1_b, (float2*)X1f, (__half2*)X1h);

    // cross-attention + LN2
    runMHA(X1h, eh, OW_CAQ, Wc + 2097152, fold + 512, false, ca_bq, ca_bk, ca_bv);
    add_ln_k<<<4096, 256>>>((const float2*)Hf, (const float2*)Hf2, (const float2*)X1f,
                            ln2_g, ln2_b, (float2*)X2f, (__half2*)X2h);

    // FFN
    {
        GemmP p{};
        p.Ah = X2h; p.Bh = Wh + OW_FC1; p.bias = fc1_b; p.Ch = Mh;
        p.K = 512; p.lda = 512; p.ldb = 2048; p.ldc = 2048;
        p.div = 1; p.biasStride = 0; p.alpha = 1.f; p.flags = 16 | 1;
        launch_gemm(false, p, 4096, 2048, 1);

        // FC2: split-K=2
        p = GemmP{};
        p.Ah = Mh; p.Ah2 = Mh; p.Bh = Wh + OW_FC2;
        p.bias = fc2_b; p.biasB = nullptr; p.biasC = nullptr;
        p.Cf = Hf;
        p.K = 1024; p.lda = 2048; p.ldb = 512; p.ldc = 512;
        p.sA1 = 1024; p.sB1 = 1024LL * 512; p.sC1 = 2097152;
        p.div = 1; p.alpha = 1.f; p.flags = 4 | 64;
        launch_gemm(false, p, 4096, 512, 2);
    }
    add_ln_k<<<4096, 256>>>((const float2*)Hf, (const float2*)Hf2, (const float2*)X2f,
                            ln3_g, ln3_b, (float2*)d_out, nullptr);
}